// round 5
// baseline (speedup 1.0000x reference)
#include <cuda_runtime.h>
#include <cuda_bf16.h>
#include <cstdint>
#include <math.h>

// Problem constants (fixed by setup_inputs): x,y [8,128,128,64] f32, blocksize 4
constexpr int B_   = 8;
constexpr int W_   = 128;
constexpr int H_   = 128;
constexpr int D_   = 64;
constexpr int BS_  = 4;
constexpr int F_   = 1024;
constexpr int NROW = 8192;
constexpr long long NX_ELEMS = (long long)B_ * W_ * H_ * D_; // 8388608

// Coarse GEMM tiling
constexpr int BM = 128;
constexpr int BN = 256;
constexpr int BK = 32;                  // bf16 elements per stage
constexpr int NTILES_N = NROW / BN;     // 32
constexpr int NTILES_M = NROW / BM;     // 64
constexpr int NST = F_ / BK;            // 32 stages (single hi*hi segment)
constexpr int NBUF = 4;

constexpr int ROWB = 80;                // padded row bytes (64B data + 16 pad)
constexpr int AOFF = 0;
constexpr int BOFF = BM * ROWB;
constexpr int STAGE = (BM + BN) * ROWB;            // 30720
constexpr int SMEM_TOTAL = NBUF * STAGE;           // 122880

constexpr float TAU = 1e-3f;            // ambiguity margin (>8 sigma of coarse err)

// Scratch (__device__ globals; allocation-free rule)
__device__ __nv_bfloat16 g_Xh[NROW * F_];
__device__ __nv_bfloat16 g_Yh[NROW * F_];
__device__ float g_Xn[NROW * F_];
__device__ float g_Yn[NROW * F_];
__device__ float g_pm [NTILES_N * NROW];
__device__ float g_pm2[NTILES_N * NROW];
__device__ int   g_pi [NTILES_N * NROW];
__device__ float g_rmax[NROW];
__device__ int   g_ridx[NROW];
__device__ int   g_fixrows[NROW];
__device__ int   g_nfix;
__device__ unsigned long long g_fixkey[NROW];

// ---------------------------------------------------------------------------
// helpers
// ---------------------------------------------------------------------------
__device__ __forceinline__ uint32_t smem_u32(const void* p) {
    uint32_t a;
    asm("{ .reg .u64 t; cvta.to.shared.u64 t, %1; cvt.u32.u64 %0, t; }"
        : "=r"(a) : "l"(p));
    return a;
}

#define CP16(dst, src) \
    asm volatile("cp.async.cg.shared.global [%0], [%1], 16;" \
                 :: "r"(dst), "l"(src) : "memory")

#define LDS32(v, a) \
    asm volatile("ld.shared.b32 %0, [%1];" : "=r"(v) : "r"(a))

#define MMA16816(d, a, b) \
    asm volatile("mma.sync.aligned.m16n8k16.row.col.f32.bf16.bf16.f32 " \
        "{%0,%1,%2,%3}, {%4,%5,%6,%7}, {%8,%9}, {%0,%1,%2,%3};" \
        : "+f"((d)[0]), "+f"((d)[1]), "+f"((d)[2]), "+f"((d)[3]) \
        : "r"((a)[0]), "r"((a)[1]), "r"((a)[2]), "r"((a)[3]), \
          "r"((b)[0]), "r"((b)[1]))

__device__ __forceinline__ unsigned long long packkey(float v, int idx) {
    unsigned u = __float_as_uint(v);
    u = (u & 0x80000000u) ? ~u : (u | 0x80000000u);
    return ((unsigned long long)u << 32) | (unsigned)(0x7FFFFFFF - idx);
}

// ---------------------------------------------------------------------------
// Kernel 1: combine (4x4xD block gather) + normalize; writes bf16 hi + fp32
// ---------------------------------------------------------------------------
__global__ void norm_combine_kernel(const float* __restrict__ x,
                                    const float* __restrict__ y) {
    if (blockIdx.x == 0 && threadIdx.x == 0) g_nfix = 0;

    int r = blockIdx.x;
    const float* src;
    bool isx;
    if (r < NROW) { src = x; isx = true; }
    else          { r -= NROW; src = y; isx = false; }

    const int b  = r >> 10;
    const int wb = (r >> 5) & 31;
    const int hb = r & 31;
    const int t  = threadIdx.x;

    float v[4];
#pragma unroll
    for (int j = 0; j < 4; j++) {
        int f = t + j * 256;
        int a = f >> 8;
        int c = (f >> 6) & 3;
        int d = f & 63;
        v[j] = src[((b * W_ + wb * BS_ + a) * H_ + hb * BS_ + c) * D_ + d];
    }

    __shared__ float red[8];
    __shared__ float bcast;

    float s = v[0] + v[1] + v[2] + v[3];
#pragma unroll
    for (int o = 16; o > 0; o >>= 1) s += __shfl_xor_sync(0xffffffffu, s, o);
    if ((t & 31) == 0) red[t >> 5] = s;
    __syncthreads();
    if (t < 32) {
        float z = (t < 8) ? red[t] : 0.0f;
#pragma unroll
        for (int o = 4; o > 0; o >>= 1) z += __shfl_xor_sync(0xffffffffu, z, o);
        if (t == 0) bcast = z;
    }
    __syncthreads();
    const float mean = bcast * (1.0f / F_);
    __syncthreads();

    float q = 0.0f;
#pragma unroll
    for (int j = 0; j < 4; j++) { float u = v[j] - mean; q += u * u; }
#pragma unroll
    for (int o = 16; o > 0; o >>= 1) q += __shfl_xor_sync(0xffffffffu, q, o);
    if ((t & 31) == 0) red[t >> 5] = q;
    __syncthreads();
    if (t < 32) {
        float z = (t < 8) ? red[t] : 0.0f;
#pragma unroll
        for (int o = 4; o > 0; o >>= 1) z += __shfl_xor_sync(0xffffffffu, z, o);
        if (t == 0) bcast = z;
    }
    __syncthreads();
    const float scale = 1.0f / (sqrtf(bcast) + 1e-5f);

    long long base = (long long)r * F_;
#pragma unroll
    for (int j = 0; j < 4; j++) {
        float w = (v[j] - mean) * scale;
        long long o = base + t + j * 256;
        if (isx) { g_Xh[o] = __float2bfloat16(w); g_Xn[o] = w; }
        else     { g_Yh[o] = __float2bfloat16(w); g_Yn[o] = w; }
    }
}

// ---------------------------------------------------------------------------
// Kernel 2: coarse bf16 GEMM (hi*hi only), fused per-row top-2 + argmax.
// 8 warps = 2(M) x 4(N), 64x64 warp tiles. 4-stage cp.async pipeline with
// constant group count (empty commits at tail) so wait_group 2 is exact.
// ---------------------------------------------------------------------------
__global__ void __launch_bounds__(256, 1) gemm_argmax_mma() {
    extern __shared__ __align__(128) char smem[];
    const uint32_t sb = smem_u32(smem);

    const int tid  = threadIdx.x;
    const int wid  = tid >> 5;
    const int lane = tid & 31;
    const int mw   = wid >> 2;
    const int nw   = wid & 3;
    const int n0   = blockIdx.x * BN;
    const int r0   = blockIdx.y * BM;

    float acc[4][8][4];
#pragma unroll
    for (int mt = 0; mt < 4; mt++)
#pragma unroll
        for (int nt = 0; nt < 8; nt++)
#pragma unroll
            for (int k = 0; k < 4; k++) acc[mt][nt][k] = 0.0f;

    auto issue = [&](int s) {
        const int k0 = s * BK;
        const uint32_t base = sb + (s & (NBUF - 1)) * STAGE;
#pragma unroll
        for (int j = 0; j < 2; j++) {
            int idx = tid + j * 256;
            int m = idx >> 2, ch = idx & 3;
            CP16(base + AOFF + m * ROWB + ch * 16,
                 g_Xh + (long long)(r0 + m) * F_ + k0 + ch * 8);
        }
#pragma unroll
        for (int j = 0; j < 4; j++) {
            int idx = tid + j * 256;
            int n = idx >> 2, ch = idx & 3;
            CP16(base + BOFF + n * ROWB + ch * 16,
                 g_Yh + (long long)(n0 + n) * F_ + k0 + ch * 8);
        }
        asm volatile("cp.async.commit_group;" ::: "memory");
    };

    issue(0); issue(1); issue(2);

    const uint32_t arow = (uint32_t)(mw * 64 + (lane >> 2)) * ROWB + (lane & 3) * 4;
    const uint32_t brow = (uint32_t)(nw * 64 + (lane >> 2)) * ROWB + (lane & 3) * 4;

    for (int s = 0; s < NST; s++) {
        // committed groups before this wait = s + 3 (empties keep it exact)
        asm volatile("cp.async.wait_group 2;" ::: "memory");
        __syncthreads();
        if (s + 3 < NST) issue(s + 3);
        else asm volatile("cp.async.commit_group;" ::: "memory");

        const uint32_t Ab = sb + (s & (NBUF - 1)) * STAGE + AOFF;
        const uint32_t Bb = sb + (s & (NBUF - 1)) * STAGE + BOFF;

#pragma unroll
        for (int ks = 0; ks < 2; ks++) {
            uint32_t af[4][4];
#pragma unroll
            for (int mt = 0; mt < 4; mt++) {
                uint32_t a0 = Ab + arow + mt * (16 * ROWB) + ks * 32;
                LDS32(af[mt][0], a0);
                LDS32(af[mt][1], a0 + 8 * ROWB);
                LDS32(af[mt][2], a0 + 16);
                LDS32(af[mt][3], a0 + 8 * ROWB + 16);
            }
            uint32_t bf_[8][2];
#pragma unroll
            for (int nt = 0; nt < 8; nt++) {
                uint32_t b0 = Bb + brow + nt * (8 * ROWB) + ks * 32;
                LDS32(bf_[nt][0], b0);
                LDS32(bf_[nt][1], b0 + 16);
            }
#pragma unroll
            for (int mt = 0; mt < 4; mt++)
#pragma unroll
                for (int nt = 0; nt < 8; nt++)
                    MMA16816(acc[mt][nt], af[mt], bf_[nt]);
        }
    }
    __syncthreads();

    // ---- per-row top-2 within tile (first-max tie rules on argmax) ----
    __shared__ float redv [4][BM];
    __shared__ float redv2[4][BM];
    __shared__ int   redi [4][BM];

#pragma unroll
    for (int mt = 0; mt < 4; mt++) {
#pragma unroll
        for (int h = 0; h < 2; h++) {
            float v1 = -1e30f, v2 = -1e30f;
            int   i1 = 0;
#pragma unroll
            for (int nt = 0; nt < 8; nt++) {
#pragma unroll
                for (int c = 0; c < 2; c++) {
                    float v = acc[mt][nt][h * 2 + c];
                    int gc = n0 + nw * 64 + nt * 8 + (lane & 3) * 2 + c;
                    if (v > v1)      { v2 = v1; v1 = v; i1 = gc; }
                    else if (v > v2) { v2 = v; }
                }
            }
#pragma unroll
            for (int o = 1; o < 4; o <<= 1) {
                float ov1 = __shfl_xor_sync(0xffffffffu, v1, o);
                int   oi1 = __shfl_xor_sync(0xffffffffu, i1, o);
                float ov2 = __shfl_xor_sync(0xffffffffu, v2, o);
                if (ov1 > v1 || (ov1 == v1 && oi1 < i1)) {
                    v2 = fmaxf(v1, ov2); v1 = ov1; i1 = oi1;
                } else {
                    v2 = fmaxf(v2, ov1);
                }
            }
            if ((lane & 3) == 0) {
                int rl = mw * 64 + mt * 16 + h * 8 + (lane >> 2);
                redv [nw][rl] = v1;
                redv2[nw][rl] = v2;
                redi [nw][rl] = i1;
            }
        }
    }
    __syncthreads();

    if (tid < BM) {
        float v1 = redv[0][tid], v2 = redv2[0][tid];
        int   i1 = redi[0][tid];
#pragma unroll
        for (int w = 1; w < 4; w++) {
            float pv1 = redv[w][tid], pv2 = redv2[w][tid];
            int   pi1 = redi[w][tid];
            if (pv1 > v1 || (pv1 == v1 && pi1 < i1)) {
                v2 = fmaxf(v1, pv2); v1 = pv1; i1 = pi1;
            } else {
                v2 = fmaxf(v2, pv1);
            }
        }
        g_pm [blockIdx.x * NROW + r0 + tid] = v1;
        g_pm2[blockIdx.x * NROW + r0 + tid] = v2;
        g_pi [blockIdx.x * NROW + r0 + tid] = i1;
    }
}

// ---------------------------------------------------------------------------
// Kernel 3: fold N-tile partials per row; build fix list for ambiguous rows
// ---------------------------------------------------------------------------
__global__ void reduce_fixlist_kernel() {
    int r = blockIdx.x * 256 + threadIdx.x;
    float v1 = g_pm[r], v2 = g_pm2[r];
    int   i1 = g_pi[r];
    for (int nt = 1; nt < NTILES_N; nt++) {
        float pv1 = g_pm[nt * NROW + r], pv2 = g_pm2[nt * NROW + r];
        int   pi1 = g_pi[nt * NROW + r];
        if (pv1 > v1 || (pv1 == v1 && pi1 < i1)) {
            v2 = fmaxf(v1, pv2); v1 = pv1; i1 = pi1;
        } else {
            v2 = fmaxf(v2, pv1);
        }
    }
    g_ridx[r] = i1;
    g_fixkey[r] = 0ull;
    if (v1 - v2 < TAU) {
        int p = atomicAdd(&g_nfix, 1);
        g_fixrows[p] = r;
    }
}

// ---------------------------------------------------------------------------
// Kernel 4: exact fp32 rescan for ambiguous rows. grid (128 row-tiles of 64,
// 32 col-tiles of 256). Full-capacity grid; idle CTAs exit.
// ---------------------------------------------------------------------------
__global__ void __launch_bounds__(256) fixup_kernel() {
    const int nfix = g_nfix;
    const int rt = blockIdx.x;
    if (rt * 64 >= nfix) return;
    const int n0 = blockIdx.y * 256;

    __shared__ float Xs[16][68];
    __shared__ float Ys[16][260];
    __shared__ int   rows[64];

    const int tid = threadIdx.x;
    if (tid < 64) {
        int fi = rt * 64 + tid;
        rows[tid] = g_fixrows[fi < nfix ? fi : (nfix - 1)];
    }
    __syncthreads();

    const int ty = tid >> 4;   // 0..15 -> 4 rows each
    const int tx = tid & 15;   // 0..15 -> 16 cols each

    float acc[4][16];
#pragma unroll
    for (int i = 0; i < 4; i++)
#pragma unroll
        for (int j = 0; j < 16; j++) acc[i][j] = 0.0f;

    const int am = tid >> 2, akq = (tid & 3) * 4;

    for (int k0 = 0; k0 < F_; k0 += 16) {
        float4 av = *(const float4*)&g_Xn[(long long)rows[am] * F_ + k0 + akq];
        float4 b4[4];
#pragma unroll
        for (int q = 0; q < 4; q++)
            b4[q] = *(const float4*)&g_Yn[(long long)(n0 + tid) * F_ + k0 + q * 4];
        __syncthreads();
        Xs[akq + 0][am] = av.x;
        Xs[akq + 1][am] = av.y;
        Xs[akq + 2][am] = av.z;
        Xs[akq + 3][am] = av.w;
#pragma unroll
        for (int q = 0; q < 4; q++) {
            Ys[q * 4 + 0][tid] = b4[q].x;
            Ys[q * 4 + 1][tid] = b4[q].y;
            Ys[q * 4 + 2][tid] = b4[q].z;
            Ys[q * 4 + 3][tid] = b4[q].w;
        }
        __syncthreads();
#pragma unroll
        for (int k = 0; k < 16; k++) {
            float4 a = *(const float4*)&Xs[k][ty * 4];
            float av_[4] = {a.x, a.y, a.z, a.w};
#pragma unroll
            for (int q = 0; q < 4; q++) {
                float4 bb = *(const float4*)&Ys[k][tx * 16 + q * 4];
                float bv[4] = {bb.x, bb.y, bb.z, bb.w};
#pragma unroll
                for (int i = 0; i < 4; i++)
#pragma unroll
                    for (int j = 0; j < 4; j++)
                        acc[i][q * 4 + j] = fmaf(av_[i], bv[j], acc[i][q * 4 + j]);
            }
        }
    }

    // per-row max/argmax, merge across tx lanes, atomic into g_fixkey
#pragma unroll
    for (int i = 0; i < 4; i++) {
        float v1 = -1e30f;
        int   i1 = 0;
#pragma unroll
        for (int j = 0; j < 16; j++) {
            float v = acc[i][j];
            int gc = n0 + tx * 16 + j;
            if (v > v1) { v1 = v; i1 = gc; }
        }
#pragma unroll
        for (int o = 1; o < 16; o <<= 1) {
            float ov = __shfl_xor_sync(0xffffffffu, v1, o);
            int   oi = __shfl_xor_sync(0xffffffffu, i1, o);
            if (ov > v1 || (ov == v1 && oi < i1)) { v1 = ov; i1 = oi; }
        }
        if (tx == 0 && rt * 64 + ty * 4 + i < nfix) {
            atomicMax(&g_fixkey[rows[ty * 4 + i]], packkey(v1, i1));
        }
    }
}

// ---------------------------------------------------------------------------
// Kernel 5: finalize — override argmax for fixed rows, exact fp32 rescore of
// the chosen sim for every row (feeds cosloss).
// ---------------------------------------------------------------------------
__global__ void finalize_kernel() {
    const int r = blockIdx.x;
    const int t = threadIdx.x;

    unsigned long long key = g_fixkey[r];
    int idx = g_ridx[r];
    if (key) idx = 0x7FFFFFFF - (int)(unsigned)(key & 0xFFFFFFFFull);
    if (t == 0) g_ridx[r] = idx;

    float s = 0.0f;
#pragma unroll
    for (int j = 0; j < 4; j++) {
        int f = t + j * 256;
        s += g_Xn[(long long)r * F_ + f] * g_Yn[(long long)idx * F_ + f];
    }
#pragma unroll
    for (int o = 16; o > 0; o >>= 1) s += __shfl_xor_sync(0xffffffffu, s, o);
    __shared__ float red[8];
    if ((t & 31) == 0) red[t >> 5] = s;
    __syncthreads();
    if (t == 0) {
        float z = 0.0f;
#pragma unroll
        for (int w = 0; w < 8; w++) z += red[w];
        g_rmax[r] = z;
    }
}

// ---------------------------------------------------------------------------
// Kernel 6: cosloss = mean(1 - rowmax)
// ---------------------------------------------------------------------------
__global__ void cosloss_kernel(float* __restrict__ out_scalar) {
    const int t = threadIdx.x;
    float s = 0.0f;
    for (int r = t; r < NROW; r += 1024) s += 1.0f - g_rmax[r];
#pragma unroll
    for (int o = 16; o > 0; o >>= 1) s += __shfl_xor_sync(0xffffffffu, s, o);
    __shared__ float red[32];
    if ((t & 31) == 0) red[t >> 5] = s;
    __syncthreads();
    if (t < 32) {
        float z = red[t];
#pragma unroll
        for (int o = 16; o > 0; o >>= 1) z += __shfl_xor_sync(0xffffffffu, z, o);
        if (t == 0) *out_scalar = z * (1.0f / NROW);
    }
}

// ---------------------------------------------------------------------------
// Kernel 7: new_x gather (scalar stores: out pointer may be 4B-aligned only)
// ---------------------------------------------------------------------------
__global__ void gather_kernel(float* __restrict__ newx) {
    const int r  = blockIdx.x;
    const int b  = r >> 10;
    const int wb = (r >> 5) & 31;
    const int hb = r & 31;

    const int idx = g_ridx[r];

    const int t  = threadIdx.x;
    const int f0 = t * 4;
    const int a  = f0 >> 8;
    const int c  = (f0 >> 6) & 3;
    const int d  = f0 & 63;

    float4 val = *(const float4*)&g_Yn[(long long)idx * F_ + f0];
    long long off = ((long long)(b * W_ + wb * BS_ + a) * H_ + hb * BS_ + c) * D_ + d;
    newx[off + 0] = val.x;
    newx[off + 1] = val.y;
    newx[off + 2] = val.z;
    newx[off + 3] = val.w;
}

// ---------------------------------------------------------------------------
extern "C" void kernel_launch(void* const* d_in, const int* in_sizes, int n_in,
                              void* d_out, int out_size) {
    const float* x = (const float*)d_in[0];
    const float* y = (const float*)d_in[1];
    float* out = (float*)d_out;

    float* newx = out;
    if ((long long)out_size > NX_ELEMS) {
        newx = out + ((long long)out_size - NX_ELEMS);
    }

    static bool attr_set = false;
    if (!attr_set) {
        cudaFuncSetAttribute(gemm_argmax_mma,
                             cudaFuncAttributeMaxDynamicSharedMemorySize, SMEM_TOTAL);
        attr_set = true;
    }

    norm_combine_kernel<<<2 * NROW, 256>>>(x, y);

    dim3 ggrid(NTILES_N, NTILES_M);
    gemm_argmax_mma<<<ggrid, 256, SMEM_TOTAL>>>();

    reduce_fixlist_kernel<<<NROW / 256, 256>>>();

    dim3 fgrid(NROW / 64, NROW / 256);
    fixup_kernel<<<fgrid, 256>>>();

    finalize_kernel<<<NROW, 256>>>();

    if ((long long)out_size > NX_ELEMS) {
        cosloss_kernel<<<1, 1024>>>(out);
    }
    gather_kernel<<<NROW, 256>>>(newx);
}